// round 1
// baseline (speedup 1.0000x reference)
#include <cuda_runtime.h>
#include <math.h>

// Problem constants (fixed by the reference):
//   T=30 steps, I=H=O=1024, gates = 4H = 4096
#define TT 30
#define HD 1024
#define G4 4096

// Scratch (allocation-free: __device__ globals).
// g_pre : pre-gates  W_ih[t]@x[t] + b_ih[t] + b_hh[t]      (30*4096 f32, ~0.5 MB)
// g_h   : double-buffered hidden state
// g_c   : cell state (owned per-index by one block per step; no race)
// g_hs  : all hidden states for the output projection
__device__ float g_pre[TT][G4];
__device__ float g_h[2][HD];
__device__ float g_c[HD];
__device__ float g_hs[TT][HD];

// Warp-cooperative dot product of two 1024-float vectors (as float4, fully
// unrolled -> 8 outstanding LDG.128 per lane for memory-level parallelism).
// Result valid in lane 0.
__device__ __forceinline__ float warp_dot1024(const float4* __restrict__ w,
                                              const float4* __restrict__ v,
                                              int lane) {
    float s = 0.f;
#pragma unroll
    for (int k = 0; k < 8; ++k) {
        float4 a = w[lane + 32 * k];
        float4 b = v[lane + 32 * k];
        s += a.x * b.x + a.y * b.y + a.z * b.z + a.w * b.w;
    }
#pragma unroll
    for (int off = 16; off; off >>= 1)
        s += __shfl_down_sync(0xffffffffu, s, off);
    return s;
}

__device__ __forceinline__ float sigmoidf_(float z) {
    return 1.f / (1.f + expf(-z));
}

// Pre-gates for step 0 only (all later steps are prefetched inside step_kernel).
// grid: 1024 blocks x 128 threads, one warp per gate-row.
__global__ void pregate0_kernel(const float* __restrict__ x,
                                const float* __restrict__ Wih,
                                const float* __restrict__ bih,
                                const float* __restrict__ bhh) {
    int warp = (blockIdx.x * blockDim.x + threadIdx.x) >> 5;  // 0..4095
    int lane = threadIdx.x & 31;
    const float4* w = (const float4*)(Wih + (size_t)warp * HD);  // t = 0
    const float4* v = (const float4*)(x);                        // x[0]
    float s = warp_dot1024(w, v, lane);
    if (lane == 0) g_pre[0][warp] = s + bih[warp] + bhh[warp];
}

// One sequential LSTM step, fused with the pre-gate prefetch for step t+1.
// grid: 2048 blocks x 128 threads (1024 when t == T-1).
//   blocks [0,1024)    : chain work — block j computes the 4 W_hh gate dots
//                        for hidden index j, then updates c[j], h[j].
//   blocks [1024,2048) : pre_gates[t+1] (4 rows per block, warp per row).
// h is double-buffered: step t reads g_h[t&1], writes g_h[(t+1)&1].
__global__ void step_kernel(int t,
                            const float* __restrict__ x,
                            const float* __restrict__ timestamps,
                            const float* __restrict__ Wih,
                            const float* __restrict__ Whh,
                            const float* __restrict__ bih,
                            const float* __restrict__ bhh) {
    int lane = threadIdx.x & 31;
    int wid  = threadIdx.x >> 5;  // 0..3

    if (blockIdx.x < HD) {
        // ---- chain block: hidden index j ----
        int j = blockIdx.x;
        float gate = 0.f;
        if (t != 0) {
            const float4* hv = (const float4*)g_h[t & 1];
            // row for gate `wid` of hidden index j
            const float4* w =
                (const float4*)(Whh + ((size_t)t * G4 + (size_t)wid * HD + j) * HD);
            gate = warp_dot1024(w, hv, lane);
        }
        __shared__ float gsh[4];
        if (lane == 0) gsh[wid] = gate;
        __syncthreads();
        if (threadIdx.x == 0) {
            float ig = gsh[0] + g_pre[t][j];
            float fg = gsh[1] + g_pre[t][HD + j];
            float gg = gsh[2] + g_pre[t][2 * HD + j];
            float og = gsh[3] + g_pre[t][3 * HD + j];
            ig = sigmoidf_(ig);
            fg = sigmoidf_(fg);
            gg = tanhf(gg);
            og = sigmoidf_(og);
            float c_prev = (t == 0) ? 0.f : g_c[j];
            float c = fg * c_prev + ig * gg;
            float h = og * tanhf(c);
            // time-decay gating: d = 2*sigmoid(-dt/60) for t < T-1, else 1
            float d = 1.f;
            if (t < TT - 1) {
                float dt = timestamps[t + 1] - timestamps[t];
                d = 2.f / (1.f + expf(dt * (1.f / 60.f)));
            }
            g_c[j] = c * d;
            g_h[(t + 1) & 1][j] = h;
            g_hs[t][j] = h;
        }
    } else if (t + 1 < TT) {
        // ---- prefetch block: pre_gates[t+1] ----
        int r = (blockIdx.x - HD) * 4 + wid;  // gate-row 0..4095
        const float4* w =
            (const float4*)(Wih + ((size_t)(t + 1) * G4 + r) * HD);
        const float4* v = (const float4*)(x + (size_t)(t + 1) * HD);
        float s = warp_dot1024(w, v, lane);
        if (lane == 0)
            g_pre[t + 1][r] = s + bih[(size_t)(t + 1) * G4 + r]
                                + bhh[(size_t)(t + 1) * G4 + r];
    }
}

// Output projection: out[t][o] = sigmoid(dot(hs[t], W_out[o,:]) + b_out[o]).
// grid: 256 blocks x 128 threads, warp per output row o; W_out row cached in
// registers (32 floats/lane), looped over all 30 timesteps (hs stays in L1/L2).
__global__ void out_kernel(const float* __restrict__ Wout,
                           const float* __restrict__ bout,
                           float* __restrict__ out) {
    int o    = (blockIdx.x * blockDim.x + threadIdx.x) >> 5;  // 0..1023
    int lane = threadIdx.x & 31;
    const float4* w = (const float4*)(Wout + (size_t)o * HD);
    float4 wr[8];
#pragma unroll
    for (int k = 0; k < 8; ++k) wr[k] = w[lane + 32 * k];
    float bo = bout[o];
    for (int t = 0; t < TT; ++t) {
        const float4* hv = (const float4*)g_hs[t];
        float s = 0.f;
#pragma unroll
        for (int k = 0; k < 8; ++k) {
            float4 b = hv[lane + 32 * k];
            s += wr[k].x * b.x + wr[k].y * b.y + wr[k].z * b.z + wr[k].w * b.w;
        }
#pragma unroll
        for (int off = 16; off; off >>= 1)
            s += __shfl_down_sync(0xffffffffu, s, off);
        if (lane == 0) out[t * HD + o] = sigmoidf_(s + bo);
    }
}

extern "C" void kernel_launch(void* const* d_in, const int* in_sizes, int n_in,
                              void* d_out, int out_size) {
    const float* x    = (const float*)d_in[0];  // [30,1024]
    const float* ts   = (const float*)d_in[1];  // [30]
    const float* Wih  = (const float*)d_in[2];  // [30,4096,1024]
    const float* Whh  = (const float*)d_in[3];  // [30,4096,1024]
    const float* bih  = (const float*)d_in[4];  // [30,4096]
    const float* bhh  = (const float*)d_in[5];  // [30,4096]
    const float* Wout = (const float*)d_in[6];  // [1024,1024]
    const float* bout = (const float*)d_in[7];  // [1024]
    float* out = (float*)d_out;                 // [30,1024]

    pregate0_kernel<<<1024, 128>>>(x, Wih, bih, bhh);
    for (int t = 0; t < TT; ++t) {
        int nblocks = (t + 1 < TT) ? 2048 : 1024;
        step_kernel<<<nblocks, 128>>>(t, x, ts, Wih, Whh, bih, bhh);
    }
    out_kernel<<<256, 128>>>(Wout, bout, out);
}

// round 13
// speedup vs baseline: 1.3015x; 1.3015x over previous
#include <cuda_runtime.h>
#include <math.h>

// T=30 steps, I=H=O=1024, gates = 4H = 4096
#define TT 30
#define HD 1024
#define G4 4096
#define NCTA 296                 // one balanced wave: <=2 CTAs/SM on 148-152 SMs
#define NTHR 256                 // 8 warps/CTA
#define NWARP (NCTA * 8)         // 2368 warps
#define NCHAIN 1024              // chain warp-tasks (one per hidden index)
#define NPREF (NWARP - NCHAIN)   // 1344 pref warps covering 4096 Wih rows

// Scratch (__device__ globals; no allocation).
__device__ float g_pre[TT][G4];    // W_ih[t]@x[t] + b_ih[t] + b_hh[t]  (t>=1)
__device__ float g_h[2][HD];       // double-buffered hidden state
__device__ float g_c[HD];          // cell state (per-j exclusive writer)
__device__ float g_hs[TT][HD];     // all hidden states for output proj

__device__ __forceinline__ float sigmoidf_(float z) {
    return 1.f / (1.f + expf(-z));
}

__device__ __forceinline__ float warp_reduce(float s) {
#pragma unroll
    for (int off = 16; off; off >>= 1)
        s += __shfl_down_sync(0xffffffffu, s, off);
    return s;
}

// Pre-gates for rows r and r+1 (paired for 2x weight-load MLP).
__device__ __forceinline__ void pregate_row2(int t, int r,
                                             const float* __restrict__ x,
                                             const float* __restrict__ Wih,
                                             const float* __restrict__ bih,
                                             const float* __restrict__ bhh,
                                             int lane) {
    const float4* v  = (const float4*)(x + (size_t)t * HD);
    const float4* w0 = (const float4*)(Wih + ((size_t)t * G4 + r) * HD);
    const float4* w1 = w0 + 256;
    float s0 = 0.f, s1 = 0.f;
#pragma unroll
    for (int k = 0; k < 8; ++k) {
        float4 b  = v[lane + 32 * k];
        float4 a0 = __ldcs(&w0[lane + 32 * k]);
        float4 a1 = __ldcs(&w1[lane + 32 * k]);
        s0 += a0.x * b.x + a0.y * b.y + a0.z * b.z + a0.w * b.w;
        s1 += a1.x * b.x + a1.y * b.y + a1.z * b.z + a1.w * b.w;
    }
    s0 = warp_reduce(s0);
    s1 = warp_reduce(s1);
    if (lane == 0) {
        size_t base = (size_t)t * G4 + r;
        g_pre[t][r]     = s0 + bih[base]     + bhh[base];
        g_pre[t][r + 1] = s1 + bih[base + 1] + bhh[base + 1];
    }
}

// Single-row variant (slice remainder).
__device__ __forceinline__ void pregate_row(int t, int r,
                                            const float* __restrict__ x,
                                            const float* __restrict__ Wih,
                                            const float* __restrict__ bih,
                                            const float* __restrict__ bhh,
                                            int lane) {
    const float4* v = (const float4*)(x + (size_t)t * HD);
    const float4* w = (const float4*)(Wih + ((size_t)t * G4 + r) * HD);
    float s = 0.f;
#pragma unroll
    for (int k = 0; k < 8; ++k) {
        float4 b = v[lane + 32 * k];
        float4 a = __ldcs(&w[lane + 32 * k]);
        s += a.x * b.x + a.y * b.y + a.z * b.z + a.w * b.w;
    }
    s = warp_reduce(s);
    if (lane == 0) {
        size_t base = (size_t)t * G4 + r;
        g_pre[t][r] = s + bih[base] + bhh[base];
    }
}

// ---------------------------------------------------------------------------
// One sequential step. Static, per-SM-balanced warp assignment:
//   chain warps (1024, uniformly interleaved): 4 gate rows of one hidden j.
//     t==0: rows of Wih[0] against x[0] (pre-gate fused; g_pre[0] unused)
//     t>=1: rows of Whh[t] against h[t-1], combined with g_pre[t] in epilogue
//   pref warps (1344): contiguous 3-4 row slice of Wih[t+1], processed in
//     pairs for doubled weight-load MLP.
// is_chain(w) <=> floor((w+1)*1024/2368) > floor(w*1024/2368); j = that floor.
// ---------------------------------------------------------------------------
__global__ __launch_bounds__(NTHR, 2)
void step_kernel(int t,
                 const float* __restrict__ x,
                 const float* __restrict__ timestamps,
                 const float* __restrict__ Wih,
                 const float* __restrict__ Whh,
                 const float* __restrict__ bih,
                 const float* __restrict__ bhh) {
    int w    = blockIdx.x * (NTHR / 32) + (threadIdx.x >> 5);  // 0..2367
    int lane = threadIdx.x & 31;

    unsigned fw  = ((unsigned)w * NCHAIN) / NWARP;        // chain count < w
    unsigned fw1 = ((unsigned)(w + 1) * NCHAIN) / NWARP;

    if (fw1 > fw) {
        // ---- chain warp: hidden index j = fw ----
        int j = (int)fw;
        // t==0: gates come from Wih[0] @ x[0]; t>=1: from Whh[t] @ h[t-1].
        const float4* hv = (t == 0) ? (const float4*)x
                                    : (const float4*)g_h[t & 1];
        const float4* wp = (t == 0)
            ? (const float4*)(Wih + (size_t)j * HD)
            : (const float4*)(Whh + ((size_t)t * G4 + j) * HD);
        float s0 = 0.f, s1 = 0.f, s2 = 0.f, s3 = 0.f;
        // gate-row stride: 1024 rows * 256 float4 = 262144 float4
#pragma unroll 4
        for (int k = 0; k < 8; ++k) {
            float4 b  = hv[lane + 32 * k];
            float4 a0 = __ldcs(&wp[lane + 32 * k]);
            float4 a1 = __ldcs(&wp[262144 + lane + 32 * k]);
            float4 a2 = __ldcs(&wp[524288 + lane + 32 * k]);
            float4 a3 = __ldcs(&wp[786432 + lane + 32 * k]);
            s0 += a0.x * b.x + a0.y * b.y + a0.z * b.z + a0.w * b.w;
            s1 += a1.x * b.x + a1.y * b.y + a1.z * b.z + a1.w * b.w;
            s2 += a2.x * b.x + a2.y * b.y + a2.z * b.z + a2.w * b.w;
            s3 += a3.x * b.x + a3.y * b.y + a3.z * b.z + a3.w * b.w;
        }
        s0 = warp_reduce(s0);
        s1 = warp_reduce(s1);
        s2 = warp_reduce(s2);
        s3 = warp_reduce(s3);
        if (lane == 0) {
            float p0, p1, p2, p3;
            if (t == 0) {
                // biases directly (pre-gate fused into this warp)
                p0 = bih[j]          + bhh[j];
                p1 = bih[HD + j]     + bhh[HD + j];
                p2 = bih[2 * HD + j] + bhh[2 * HD + j];
                p3 = bih[3 * HD + j] + bhh[3 * HD + j];
            } else {
                p0 = g_pre[t][j];
                p1 = g_pre[t][HD + j];
                p2 = g_pre[t][2 * HD + j];
                p3 = g_pre[t][3 * HD + j];
            }
            float ig = sigmoidf_(s0 + p0);
            float fg = sigmoidf_(s1 + p1);
            float gg = tanhf    (s2 + p2);
            float og = sigmoidf_(s3 + p3);
            float c_prev = (t == 0) ? 0.f : g_c[j];
            float c = fg * c_prev + ig * gg;
            float h = og * tanhf(c);
            float d = 1.f;
            if (t < TT - 1) {
                float dt = timestamps[t + 1] - timestamps[t];
                d = 2.f / (1.f + expf(dt * (1.f / 60.f)));
            }
            g_c[j] = c * d;
            g_h[(t + 1) & 1][j] = h;
            g_hs[t][j] = h;
        }
    } else if (t + 1 < TT) {
        // ---- pref warp: rows [p*4096/1344, (p+1)*4096/1344) of Wih[t+1] ----
        int p  = w - (int)fw;                       // 0..1343
        int r0 = (int)(((unsigned)p * G4) / NPREF);
        int r1 = (int)(((unsigned)(p + 1) * G4) / NPREF);
        int r  = r0;
        for (; r + 1 < r1; r += 2)
            pregate_row2(t + 1, r, x, Wih, bih, bhh, lane);
        if (r < r1)
            pregate_row(t + 1, r, x, Wih, bih, bhh, lane);
    }
}

// ---------------------------------------------------------------------------
// Output projection: out[t][o] = sigmoid(hs[t] . Wout[o] + bout[o]).
// Warp per output row, Wout row cached in registers, loop over T.
// ---------------------------------------------------------------------------
__global__ __launch_bounds__(128)
void out_kernel(const float* __restrict__ Wout,
                const float* __restrict__ bout,
                float* __restrict__ out) {
    int o    = (blockIdx.x * blockDim.x + threadIdx.x) >> 5;  // 0..1023
    int lane = threadIdx.x & 31;
    const float4* w = (const float4*)(Wout + (size_t)o * HD);
    float4 wr[8];
#pragma unroll
    for (int k = 0; k < 8; ++k) wr[k] = w[lane + 32 * k];
    float bo = bout[o];
    for (int t = 0; t < TT; ++t) {
        const float4* hv = (const float4*)g_hs[t];
        float s = 0.f;
#pragma unroll
        for (int k = 0; k < 8; ++k) {
            float4 b = hv[lane + 32 * k];
            s += wr[k].x * b.x + wr[k].y * b.y + wr[k].z * b.z + wr[k].w * b.w;
        }
        s = warp_reduce(s);
        if (lane == 0) out[t * HD + o] = sigmoidf_(s + bo);
    }
}

extern "C" void kernel_launch(void* const* d_in, const int* in_sizes, int n_in,
                              void* d_out, int out_size) {
    const float* x    = (const float*)d_in[0];  // [30,1024]
    const float* ts   = (const float*)d_in[1];  // [30]
    const float* Wih  = (const float*)d_in[2];  // [30,4096,1024]
    const float* Whh  = (const float*)d_in[3];  // [30,4096,1024]
    const float* bih  = (const float*)d_in[4];  // [30,4096]
    const float* bhh  = (const float*)d_in[5];  // [30,4096]
    const float* Wout = (const float*)d_in[6];  // [1024,1024]
    const float* bout = (const float*)d_in[7];  // [1024]
    float* out = (float*)d_out;                 // [30,1024]

    for (int t = 0; t < TT; ++t)
        step_kernel<<<NCTA, NTHR>>>(t, x, ts, Wih, Whh, bih, bhh);
    out_kernel<<<256, 128>>>(Wout, bout, out);
}